// round 9
// baseline (speedup 1.0000x reference)
#include <cuda_runtime.h>
#include <cstdlib>

// ---------------------------------------------------------------------------
// EnhancedSocialRecommender — low-footprint scatter pipeline (~56 MB scratch)
// U=100000, I=150000, D=64, 2M ui edges, 1M social edges, B=4096
//
// Memory strategy: the module data segment is lazily allocated inside the
// harness's checkpoint and rounds up to a 64 MiB-granular reservation
// (observed: 214MB->256MiB, 122MB->128MiB, both rejected). Total static
// scratch here is ~56 MB -> 64 MiB reservation, the minimum reachable in
// full fp32. Achieved by:
//   * one 25.6 MB arena reused as i1-half -> u1 -> Z -> c1 (liveness-packed)
//   * S@(X@W) == (S@X)@W : scatter raw rows, apply W per-row in a fused
//     GEMV+gate kernel (no T array)
//   * LightGCN i1 computed in two 32-column halves (columns independent)
//
// Math (matches reference):
//   u1 = ui@Ei + 0.1Eu ; i1 = iu@Eu + 0.1Ei ; u2 = ui@i1 + 0.1Eu
//   i2 (sel) = iu@u1 + 0.1Ei ; c1 = gate(u2 + (S@u2)@W0, u2)
//   c2 (sel) = gate(c1 + (S@c1)@W1, c1)
//   uw = nw0*Eu + nw1*u1 + nw2*u2 ; sw = nw0*u2 + nw1*c1 + nw2*c2
//   fused = lrelu(LN([uw|sw]@mpW + mpb)) ; itw = nw0*Ei + nw1*i1 + nw2*i2
//   out[b] = dot(fused[users[b]], itw[pos_items[b]])
// ---------------------------------------------------------------------------

#define U_N 100000
#define I_N 150000
#define NNZ_UI 2000000
#define NNZ_S 1000000
#define BSZ 4096

// ------------------------- device scratch (~56 MB) -------------------------
__device__ float g_u2 [U_N * 64];     // 25.6 MB, live whole run
__device__ float g_buf[U_N * 64];     // 25.6 MB arena: i1h(I*32=4.8M floats) -> u1 -> Z -> c1
__device__ float g_itw[BSZ * 64];     // 1 MB : partial item_weighted per b
__device__ float g_i2b[BSZ * 64];     // 1 MB : iu@u1 accumulated per item-slot
__device__ float g_zbf[BSZ * 64];     // 1 MB : S@c1 accumulated per user-slot
__device__ float g_fin[BSZ * 128];    // 2 MB : [uw | sw]
__device__ float g_fus[BSZ * 64];     // 1 MB
__device__ int   g_slot_u[U_N];       // 0.4 MB
__device__ int   g_slot_i[I_N];       // 0.6 MB

// ------------------------- helpers ----------------------------------------
static __device__ __forceinline__ float warpSum(float v) {
#pragma unroll
    for (int o = 16; o; o >>= 1) v += __shfl_xor_sync(0xffffffffu, v, o);
    return v;
}

static __device__ __forceinline__ void softmax3(const float* __restrict__ lw,
                                                float& n0, float& n1, float& n2) {
    float l0 = lw[0], l1 = lw[1], l2 = lw[2];
    float m = fmaxf(l0, fmaxf(l1, l2));
    float e0 = expf(l0 - m), e1 = expf(l1 - m), e2 = expf(l2 - m);
    float inv = 1.0f / (e0 + e1 + e2);
    n0 = e0 * inv; n1 = e1 * inv; n2 = e2 * inv;
}

static __device__ __forceinline__ float lrelu(float x) {
    return x > 0.0f ? x : 0.01f * x;
}

// LN + lrelu + sigmoid on h (cols lane, lane+32)
static __device__ __forceinline__ void gate_from_h(float h0, float h1,
                                                   const float* __restrict__ hog,
                                                   const float* __restrict__ hobeta,
                                                   int lane, float& gt0, float& gt1) {
    float s = warpSum(h0 + h1);
    float q = warpSum(h0 * h0 + h1 * h1);
    float mu = s * (1.0f / 64.0f);
    float var = q * (1.0f / 64.0f) - mu * mu;
    float inv = rsqrtf(var + 1e-5f);
    float y0 = lrelu((h0 - mu) * inv * hog[lane] + hobeta[lane]);
    float y1 = lrelu((h1 - mu) * inv * hog[lane + 32] + hobeta[lane + 32]);
    gt0 = 1.0f / (1.0f + expf(-y0));
    gt1 = 1.0f / (1.0f + expf(-y1));
}

// ------------------------- init / slots ------------------------------------
__global__ void k_init(const float* __restrict__ Eu) {
    int i = blockIdx.x * blockDim.x + threadIdx.x;
    int stride = gridDim.x * blockDim.x;
    const float4* Eu4 = (const float4*)Eu;
    float4* u24 = (float4*)g_u2;
    for (int j = i; j < U_N * 16; j += stride) {
        float4 v = Eu4[j];
        v.x *= 0.1f; v.y *= 0.1f; v.z *= 0.1f; v.w *= 0.1f;
        u24[j] = v;
    }
    for (int j = i; j < U_N; j += stride) g_slot_u[j] = -1;
    for (int j = i; j < I_N; j += stride) g_slot_i[j] = -1;
    float4 z = make_float4(0.f, 0.f, 0.f, 0.f);
    float4* ib = (float4*)g_i2b;
    float4* zb = (float4*)g_zbf;
    for (int j = i; j < BSZ * 16; j += stride) { ib[j] = z; zb[j] = z; }
}

__global__ void k_slots(const int* __restrict__ users, const int* __restrict__ pos_items) {
    int b = blockIdx.x * blockDim.x + threadIdx.x;
    if (b < BSZ) {
        g_slot_u[users[b]] = b;      // duplicates: any winner valid (rows identical)
        g_slot_i[pos_items[b]] = b;
    }
}

// ------------------------- column-half LightGCN ----------------------------
// buf (as i1h, I x 32) = 0.1 * Ei[:, hbase:hbase+32]
__global__ void k_i1h_init(const float* __restrict__ Ei, int hbase) {
    int i = blockIdx.x * blockDim.x + threadIdx.x;
    int stride = gridDim.x * blockDim.x;
    for (int j = i; j < I_N * 32; j += stride) {
        int row = j >> 5, c = j & 31;
        g_buf[j] = 0.1f * __ldg(Ei + row * 64 + hbase + c);
    }
}

// i1h[d] += w * Eu[s, hcols]   (warp per edge, 1 col per lane)
__global__ void k_edge_i1h(const int* __restrict__ src, const int* __restrict__ dst,
                           const float* __restrict__ w, const float* __restrict__ Eu,
                           int hbase) {
    int gw = (blockIdx.x * blockDim.x + threadIdx.x) >> 5;
    int lane = threadIdx.x & 31;
    int nwarps = (gridDim.x * blockDim.x) >> 5;
    for (int e = gw; e < NNZ_UI; e += nwarps) {
        int s = __ldg(src + e), d = __ldg(dst + e);
        float wt = __ldg(w + e);
        float ev = __ldg(Eu + s * 64 + hbase + lane);
        atomicAdd(&g_buf[d * 32 + lane], wt * ev);
    }
}

// u2[s, hcols] += w * i1h[d]
__global__ void k_edge_u2h(const int* __restrict__ src, const int* __restrict__ dst,
                           const float* __restrict__ w, int hbase) {
    int gw = (blockIdx.x * blockDim.x + threadIdx.x) >> 5;
    int lane = threadIdx.x & 31;
    int nwarps = (gridDim.x * blockDim.x) >> 5;
    for (int e = gw; e < NNZ_UI; e += nwarps) {
        int s = __ldg(src + e), d = __ldg(dst + e);
        float wt = __ldg(w + e);
        float iv = __ldg(&g_buf[d * 32 + lane]);
        atomicAdd(&g_u2[s * 64 + hbase + lane], wt * iv);
    }
}

// itw partial for this half: (nw0 + 0.1*nw2)*Ei + nw1*i1h at pos_items rows
__global__ void k_itw_h(const int* __restrict__ pos_items, const float* __restrict__ lw,
                        const float* __restrict__ Ei, int hbase) {
    int wi = threadIdx.x >> 5, lane = threadIdx.x & 31;
    int b = blockIdx.x * 8 + wi;
    if (b >= BSZ) return;
    int r = pos_items[b];
    float nw0, nw1, nw2;
    softmax3(lw, nw0, nw1, nw2);
    float c0 = nw0 + 0.1f * nw2;
    g_itw[b * 64 + hbase + lane] =
        c0 * __ldg(Ei + r * 64 + hbase + lane) + nw1 * g_buf[r * 32 + lane];
}

// ------------------------- u1 full + i2 + uw partial -----------------------
__global__ void k_u1_init(const float* __restrict__ Eu) {
    int i = blockIdx.x * blockDim.x + threadIdx.x;
    int stride = gridDim.x * blockDim.x;
    const float4* Eu4 = (const float4*)Eu;
    float4* b4 = (float4*)g_buf;
    for (int j = i; j < U_N * 16; j += stride) {
        float4 v = Eu4[j];
        v.x *= 0.1f; v.y *= 0.1f; v.z *= 0.1f; v.w *= 0.1f;
        b4[j] = v;
    }
}

// u1[s] += w * Ei[d]   (warp per edge, 2 cols per lane)
__global__ void k_edge_u1(const int* __restrict__ src, const int* __restrict__ dst,
                          const float* __restrict__ w, const float* __restrict__ Ei) {
    int gw = (blockIdx.x * blockDim.x + threadIdx.x) >> 5;
    int lane = threadIdx.x & 31;
    int nwarps = (gridDim.x * blockDim.x) >> 5;
    const float2* Ei2 = (const float2*)Ei;
    for (int e = gw; e < NNZ_UI; e += nwarps) {
        int s = __ldg(src + e), d = __ldg(dst + e);
        float wt = __ldg(w + e);
        float2 ev = __ldg(Ei2 + d * 32 + lane);
        atomicAdd(&g_buf[s * 64 + 2 * lane],     wt * ev.x);
        atomicAdd(&g_buf[s * 64 + 2 * lane + 1], wt * ev.y);
    }
}

// i2b[slot_i[d]] += w * u1[s]  (selected items only)
__global__ void k_edge_i2(const int* __restrict__ src, const int* __restrict__ dst,
                          const float* __restrict__ w) {
    int gw = (blockIdx.x * blockDim.x + threadIdx.x) >> 5;
    int lane = threadIdx.x & 31;
    int nwarps = (gridDim.x * blockDim.x) >> 5;
    const float2* u12 = (const float2*)g_buf;
    for (int e = gw; e < NNZ_UI; e += nwarps) {
        int d = __ldg(dst + e);
        int v = g_slot_i[d];
        if (v < 0) continue;
        int s = __ldg(src + e);
        float wt = __ldg(w + e);
        float2 uv = __ldg(u12 + s * 32 + lane);
        atomicAdd(&g_i2b[v * 64 + 2 * lane],     wt * uv.x);
        atomicAdd(&g_i2b[v * 64 + 2 * lane + 1], wt * uv.y);
    }
}

// fin[b, 0:64] = nw0*Eu[r] + nw1*u1[r]   (u1 still in buf)
__global__ void k_fin_uw(const int* __restrict__ users, const float* __restrict__ lw,
                         const float* __restrict__ Eu) {
    int wi = threadIdx.x >> 5, lane = threadIdx.x & 31;
    int b = blockIdx.x * 8 + wi;
    if (b >= BSZ) return;
    int r = users[b];
    float nw0, nw1, nw2;
    softmax3(lw, nw0, nw1, nw2);
    g_fin[b * 128 + lane]      = nw0 * __ldg(Eu + r * 64 + lane)      + nw1 * g_buf[r * 64 + lane];
    g_fin[b * 128 + lane + 32] = nw0 * __ldg(Eu + r * 64 + lane + 32) + nw1 * g_buf[r * 64 + lane + 32];
}

// ------------------------- social layer 1 ----------------------------------
__global__ void k_zero_buf() {
    int i = blockIdx.x * blockDim.x + threadIdx.x;
    int stride = gridDim.x * blockDim.x;
    float4 z = make_float4(0.f, 0.f, 0.f, 0.f);
    float4* b4 = (float4*)g_buf;
    for (int j = i; j < U_N * 16; j += stride) b4[j] = z;
}

// Z[s] += w * u2[d]
__global__ void k_edge_Z(const int* __restrict__ src, const int* __restrict__ dst,
                         const float* __restrict__ w) {
    int gw = (blockIdx.x * blockDim.x + threadIdx.x) >> 5;
    int lane = threadIdx.x & 31;
    int nwarps = (gridDim.x * blockDim.x) >> 5;
    const float2* u22 = (const float2*)g_u2;
    for (int e = gw; e < NNZ_S; e += nwarps) {
        int s = __ldg(src + e), d = __ldg(dst + e);
        float wt = __ldg(w + e);
        float2 uv = __ldg(u22 + d * 32 + lane);
        atomicAdd(&g_buf[s * 64 + 2 * lane],     wt * uv.x);
        atomicAdd(&g_buf[s * 64 + 2 * lane + 1], wt * uv.y);
    }
}

// c1 = gate(u2 + Z@W0, u2), written over Z in place (row-local)
__global__ void k_gate1(const float* __restrict__ W0, const float* __restrict__ hoW,
                        const float* __restrict__ hob, const float* __restrict__ hog,
                        const float* __restrict__ hobeta) {
    __shared__ float sW0[64 * 64];
    __shared__ float sHW[64 * 64];
    __shared__ float sRow[8][64];
    for (int i = threadIdx.x; i < 64 * 64; i += blockDim.x) { sW0[i] = W0[i]; sHW[i] = hoW[i]; }
    __syncthreads();
    int wi = threadIdx.x >> 5, lane = threadIdx.x & 31;
    int row = blockIdx.x * 8 + wi;
    if (row >= U_N) return;

    // stage Z row
    float2 zv = ((const float2*)g_buf)[row * 32 + lane];
    sRow[wi][2 * lane] = zv.x; sRow[wi][2 * lane + 1] = zv.y;
    __syncwarp();
    // ZW = Z@W0, cols (lane, lane+32)
    float zw0 = 0.f, zw1 = 0.f;
#pragma unroll
    for (int k = 0; k < 64; k++) {
        float zk = sRow[wi][k];
        zw0 = fmaf(zk, sW0[k * 64 + lane], zw0);
        zw1 = fmaf(zk, sW0[k * 64 + lane + 32], zw1);
    }
    float u20 = g_u2[row * 64 + lane], u21 = g_u2[row * 64 + lane + 32];
    float n0 = u20 + zw0, n1 = u21 + zw1;        // new1
    __syncwarp();
    sRow[wi][lane] = n0; sRow[wi][lane + 32] = n1;
    __syncwarp();
    float h0 = hob[lane], h1 = hob[lane + 32];
#pragma unroll
    for (int k = 0; k < 64; k++) {
        float nk = sRow[wi][k];
        h0 = fmaf(nk, sHW[k * 64 + lane], h0);
        h1 = fmaf(nk, sHW[k * 64 + lane + 32], h1);
    }
    float gt0, gt1;
    gate_from_h(h0, h1, hog, hobeta, lane, gt0, gt1);
    g_buf[row * 64 + lane]      = gt0 * n0 + (1.0f - gt0) * u20;
    g_buf[row * 64 + lane + 32] = gt1 * n1 + (1.0f - gt1) * u21;
}

// ------------------------- social layer 2 (selected) -----------------------
// zbf[slot_u[s]] += w * c1[d]
__global__ void k_edge_s2(const int* __restrict__ src, const int* __restrict__ dst,
                          const float* __restrict__ w) {
    int gw = (blockIdx.x * blockDim.x + threadIdx.x) >> 5;
    int lane = threadIdx.x & 31;
    int nwarps = (gridDim.x * blockDim.x) >> 5;
    const float2* c12 = (const float2*)g_buf;
    for (int e = gw; e < NNZ_S; e += nwarps) {
        int s = __ldg(src + e);
        int v = g_slot_u[s];
        if (v < 0) continue;
        int d = __ldg(dst + e);
        float wt = __ldg(w + e);
        float2 cv = __ldg(c12 + d * 32 + lane);
        atomicAdd(&g_zbf[v * 64 + 2 * lane],     wt * cv.x);
        atomicAdd(&g_zbf[v * 64 + 2 * lane + 1], wt * cv.y);
    }
}

// per selected user: gate layer 2, assemble sw and finish uw
__global__ void k_user_fin(const int* __restrict__ users, const float* __restrict__ lw,
                           const float* __restrict__ W1, const float* __restrict__ hoW,
                           const float* __restrict__ hob, const float* __restrict__ hog,
                           const float* __restrict__ hobeta) {
    __shared__ float sW1[64 * 64];
    __shared__ float sHW[64 * 64];
    __shared__ float sRow[8][64];
    for (int i = threadIdx.x; i < 64 * 64; i += blockDim.x) { sW1[i] = W1[i]; sHW[i] = hoW[i]; }
    __syncthreads();
    int wi = threadIdx.x >> 5, lane = threadIdx.x & 31;
    int b = blockIdx.x * 8 + wi;
    if (b >= BSZ) return;
    int r = users[b];
    int v = g_slot_u[r];
    float nw0, nw1, nw2;
    softmax3(lw, nw0, nw1, nw2);

    float2 zv = ((const float2*)g_zbf)[v * 32 + lane];
    sRow[wi][2 * lane] = zv.x; sRow[wi][2 * lane + 1] = zv.y;
    __syncwarp();
    float zw0 = 0.f, zw1 = 0.f;
#pragma unroll
    for (int k = 0; k < 64; k++) {
        float zk = sRow[wi][k];
        zw0 = fmaf(zk, sW1[k * 64 + lane], zw0);
        zw1 = fmaf(zk, sW1[k * 64 + lane + 32], zw1);
    }
    float c10 = g_buf[r * 64 + lane], c11 = g_buf[r * 64 + lane + 32];
    float n0 = c10 + zw0, n1 = c11 + zw1;        // new2
    __syncwarp();
    sRow[wi][lane] = n0; sRow[wi][lane + 32] = n1;
    __syncwarp();
    float h0 = hob[lane], h1 = hob[lane + 32];
#pragma unroll
    for (int k = 0; k < 64; k++) {
        float nk = sRow[wi][k];
        h0 = fmaf(nk, sHW[k * 64 + lane], h0);
        h1 = fmaf(nk, sHW[k * 64 + lane + 32], h1);
    }
    float gt0, gt1;
    gate_from_h(h0, h1, hog, hobeta, lane, gt0, gt1);
    float s20 = gt0 * n0 + (1.0f - gt0) * c10;
    float s21 = gt1 * n1 + (1.0f - gt1) * c11;

    float u20 = g_u2[r * 64 + lane], u21 = g_u2[r * 64 + lane + 32];
    g_fin[b * 128 + 64 + lane] = nw0 * u20 + nw1 * c10 + nw2 * s20;
    g_fin[b * 128 + 96 + lane] = nw0 * u21 + nw1 * c11 + nw2 * s21;
    g_fin[b * 128 + lane]      += nw2 * u20;     // finish uw
    g_fin[b * 128 + lane + 32] += nw2 * u21;
}

// ------------------------- metapath fusion ---------------------------------
__global__ void k_metapath(const float* __restrict__ mpW, const float* __restrict__ mpb,
                           const float* __restrict__ mpg, const float* __restrict__ mpbeta) {
    __shared__ float sW[128 * 64];
    __shared__ float sF[8][128];
    for (int i = threadIdx.x; i < 128 * 64; i += blockDim.x) sW[i] = mpW[i];
    __syncthreads();
    int wi = threadIdx.x >> 5, lane = threadIdx.x & 31;
    int b = blockIdx.x * 8 + wi;
    if (b >= BSZ) return;
    float4 f = ((const float4*)g_fin)[b * 32 + lane];
    sF[wi][4 * lane] = f.x; sF[wi][4 * lane + 1] = f.y;
    sF[wi][4 * lane + 2] = f.z; sF[wi][4 * lane + 3] = f.w;
    __syncwarp();
    float h0 = mpb[lane], h1 = mpb[lane + 32];
#pragma unroll
    for (int k = 0; k < 128; k++) {
        float fk = sF[wi][k];
        h0 = fmaf(fk, sW[k * 64 + lane], h0);
        h1 = fmaf(fk, sW[k * 64 + lane + 32], h1);
    }
    float s = warpSum(h0 + h1);
    float q = warpSum(h0 * h0 + h1 * h1);
    float mu = s * (1.0f / 64.0f);
    float var = q * (1.0f / 64.0f) - mu * mu;
    float inv = rsqrtf(var + 1e-5f);
    g_fus[b * 64 + lane]      = lrelu((h0 - mu) * inv * mpg[lane] + mpbeta[lane]);
    g_fus[b * 64 + lane + 32] = lrelu((h1 - mu) * inv * mpg[lane + 32] + mpbeta[lane + 32]);
}

// ------------------------- score -------------------------------------------
__global__ void k_score(const int* __restrict__ pos_items, const float* __restrict__ lw,
                        float* __restrict__ out) {
    int wi = threadIdx.x >> 5, lane = threadIdx.x & 31;
    int b = blockIdx.x * 8 + wi;
    if (b >= BSZ) return;
    int v = g_slot_i[pos_items[b]];
    float nw0, nw1, nw2;
    softmax3(lw, nw0, nw1, nw2);
    float2 fu = ((const float2*)g_fus)[b * 32 + lane];
    float2 it = ((const float2*)g_itw)[b * 32 + lane];
    float2 i2 = ((const float2*)g_i2b)[v * 32 + lane];
    float p = warpSum(fu.x * (it.x + nw2 * i2.x) + fu.y * (it.y + nw2 * i2.y));
    if (lane == 0) out[b] = p;
}

// ---------------------------------------------------------------------------
extern "C" void kernel_launch(void* const* d_in, const int* in_sizes, int n_in,
                              void* d_out, int out_size) {
    const int*   users   = (const int*)d_in[0];
    const int*   pos_it  = (const int*)d_in[1];
    const int*   ui_src  = (const int*)d_in[2];
    const int*   ui_dst  = (const int*)d_in[3];
    const float* ui_w    = (const float*)d_in[4];
    const int*   s_src   = (const int*)d_in[5];
    const int*   s_dst   = (const int*)d_in[6];
    const float* s_w     = (const float*)d_in[7];
    const float* Eu      = (const float*)d_in[8];
    const float* Ei      = (const float*)d_in[9];
    const float* lw      = (const float*)d_in[10];
    const float* Wsoc    = (const float*)d_in[11];
    const float* ho_W    = (const float*)d_in[12];
    const float* ho_b    = (const float*)d_in[13];
    const float* ho_g    = (const float*)d_in[14];
    const float* ho_beta = (const float*)d_in[15];
    const float* mp_W    = (const float*)d_in[16];
    const float* mp_b    = (const float*)d_in[17];
    const float* mp_g    = (const float*)d_in[18];
    const float* mp_beta = (const float*)d_in[19];
    float* out = (float*)d_out;

    k_init<<<1024, 256>>>(Eu);
    k_slots<<<16, 256>>>(users, pos_it);

    // LightGCN: i1 in column halves (arena), u2 accumulates full width
    for (int h = 0; h < 2; h++) {
        int hbase = h * 32;
        k_i1h_init<<<4096, 256>>>(Ei, hbase);
        k_edge_i1h<<<8192, 256>>>(ui_src, ui_dst, ui_w, Eu, hbase);
        k_edge_u2h<<<8192, 256>>>(ui_src, ui_dst, ui_w, hbase);
        k_itw_h<<<BSZ / 8, 256>>>(pos_it, lw, Ei, hbase);
    }

    // u1 full (arena), i2 at selected items, uw partial
    k_u1_init<<<1024, 256>>>(Eu);
    k_edge_u1<<<8192, 256>>>(ui_src, ui_dst, ui_w, Ei);
    k_edge_i2<<<8192, 256>>>(ui_src, ui_dst, ui_w);
    k_fin_uw<<<BSZ / 8, 256>>>(users, lw, Eu);

    // Social layer 1: Z = S@u2 (arena), fused GEMV+gate -> c1 (arena, in place)
    k_zero_buf<<<1024, 256>>>();
    k_edge_Z<<<4096, 256>>>(s_src, s_dst, s_w);
    k_gate1<<<(U_N + 7) / 8, 256>>>(Wsoc, ho_W, ho_b, ho_g, ho_beta);

    // Social layer 2 at selected users + assemble fin
    k_edge_s2<<<4096, 256>>>(s_src, s_dst, s_w);
    k_user_fin<<<BSZ / 8, 256>>>(users, lw, Wsoc + 64 * 64, ho_W, ho_b, ho_g, ho_beta);

    // metapath fusion + score
    k_metapath<<<BSZ / 8, 256>>>(mp_W, mp_b, mp_g, mp_beta);
    k_score<<<BSZ / 8, 256>>>(pos_it, lw, out);
}

// round 10
// speedup vs baseline: 1.2411x; 1.2411x over previous
#include <cuda_runtime.h>
#include <cstdlib>

// ---------------------------------------------------------------------------
// EnhancedSocialRecommender — low-footprint scatter pipeline, vectorized
// U=100000, I=150000, D=64, 2M ui edges, 1M social edges, B=4096
//
// R9 passed at 854us with scalar gathers/atomics; ncu showed L1=54.8%,
// issue=47.7% (LSU-op bound, DRAM 8.2%). This round: float4 gathers +
// float4 atomics (cc>=9.0), multiple edges per warp:
//   half-width (32 cols): 4 edges/warp, 8 lanes/edge
//   full-width (64 cols): 2 edges/warp, 16 lanes/edge
// -> 4x fewer atomic/gather lane-ops at identical byte volume.
// Scratch unchanged (~58.5 MB -> 64 MiB reservation, accepted in R9).
// ---------------------------------------------------------------------------

#define U_N 100000
#define I_N 150000
#define NNZ_UI 2000000
#define NNZ_S 1000000
#define BSZ 4096

// ------------------------- device scratch (~58.5 MB) -----------------------
__device__ float g_u2 [U_N * 64];     // 25.6 MB, live whole run
__device__ float g_buf[U_N * 64];     // 25.6 MB arena: i1h -> u1 -> Z -> c1
__device__ float g_itw[BSZ * 64];
__device__ float g_i2b[BSZ * 64];
__device__ float g_zbf[BSZ * 64];
__device__ float g_fin[BSZ * 128];
__device__ float g_fus[BSZ * 64];
__device__ int   g_slot_u[U_N];
__device__ int   g_slot_i[I_N];

// ------------------------- helpers ----------------------------------------
static __device__ __forceinline__ float warpSum(float v) {
#pragma unroll
    for (int o = 16; o; o >>= 1) v += __shfl_xor_sync(0xffffffffu, v, o);
    return v;
}

static __device__ __forceinline__ void softmax3(const float* __restrict__ lw,
                                                float& n0, float& n1, float& n2) {
    float l0 = lw[0], l1 = lw[1], l2 = lw[2];
    float m = fmaxf(l0, fmaxf(l1, l2));
    float e0 = expf(l0 - m), e1 = expf(l1 - m), e2 = expf(l2 - m);
    float inv = 1.0f / (e0 + e1 + e2);
    n0 = e0 * inv; n1 = e1 * inv; n2 = e2 * inv;
}

static __device__ __forceinline__ float lrelu(float x) {
    return x > 0.0f ? x : 0.01f * x;
}

static __device__ __forceinline__ void gate_from_h(float h0, float h1,
                                                   const float* __restrict__ hog,
                                                   const float* __restrict__ hobeta,
                                                   int lane, float& gt0, float& gt1) {
    float s = warpSum(h0 + h1);
    float q = warpSum(h0 * h0 + h1 * h1);
    float mu = s * (1.0f / 64.0f);
    float var = q * (1.0f / 64.0f) - mu * mu;
    float inv = rsqrtf(var + 1e-5f);
    float y0 = lrelu((h0 - mu) * inv * hog[lane] + hobeta[lane]);
    float y1 = lrelu((h1 - mu) * inv * hog[lane + 32] + hobeta[lane + 32]);
    gt0 = 1.0f / (1.0f + expf(-y0));
    gt1 = 1.0f / (1.0f + expf(-y1));
}

static __device__ __forceinline__ float4 scale4(float w, float4 v) {
    return make_float4(w * v.x, w * v.y, w * v.z, w * v.w);
}

// ------------------------- init / slots ------------------------------------
__global__ void k_init(const float* __restrict__ Eu) {
    int i = blockIdx.x * blockDim.x + threadIdx.x;
    int stride = gridDim.x * blockDim.x;
    const float4* Eu4 = (const float4*)Eu;
    float4* u24 = (float4*)g_u2;
    for (int j = i; j < U_N * 16; j += stride) {
        float4 v = Eu4[j];
        v.x *= 0.1f; v.y *= 0.1f; v.z *= 0.1f; v.w *= 0.1f;
        u24[j] = v;
    }
    for (int j = i; j < U_N; j += stride) g_slot_u[j] = -1;
    for (int j = i; j < I_N; j += stride) g_slot_i[j] = -1;
    float4 z = make_float4(0.f, 0.f, 0.f, 0.f);
    float4* ib = (float4*)g_i2b;
    float4* zb = (float4*)g_zbf;
    for (int j = i; j < BSZ * 16; j += stride) { ib[j] = z; zb[j] = z; }
}

__global__ void k_slots(const int* __restrict__ users, const int* __restrict__ pos_items) {
    int b = blockIdx.x * blockDim.x + threadIdx.x;
    if (b < BSZ) {
        g_slot_u[users[b]] = b;      // duplicates: any winner valid (rows identical)
        g_slot_i[pos_items[b]] = b;
    }
}

// ------------------------- column-half LightGCN ----------------------------
// buf (as i1h, I x 32) = 0.1 * Ei[:, hbase:hbase+32]
__global__ void k_i1h_init(const float* __restrict__ Ei, int hbase) {
    int i = blockIdx.x * blockDim.x + threadIdx.x;
    int stride = gridDim.x * blockDim.x;
    float4* b4 = (float4*)g_buf;
    const float4* Ei4 = (const float4*)Ei;
    for (int j = i; j < I_N * 8; j += stride) {       // 8 f4 per half row
        int row = j >> 3, qq = j & 7;
        float4 v = __ldg(Ei4 + row * 16 + (hbase >> 2) + qq);
        v.x *= 0.1f; v.y *= 0.1f; v.z *= 0.1f; v.w *= 0.1f;
        b4[row * 8 + qq] = v;
    }
}

// i1h[d] += w * Eu[s, hcols]   (4 edges/warp, 8 lanes/edge, f4 ops)
__global__ void k_edge_i1h(const int* __restrict__ src, const int* __restrict__ dst,
                           const float* __restrict__ w, const float* __restrict__ Eu,
                           int hbase) {
    int tid = blockIdx.x * blockDim.x + threadIdx.x;
    int warp = tid >> 5, lane = tid & 31;
    int sub = lane >> 3, q = lane & 7;
    int nw = (gridDim.x * blockDim.x) >> 5;
    int hq = hbase >> 2;
    const float4* Eu4 = (const float4*)Eu;
    float4* B4 = (float4*)g_buf;
    for (int base = warp * 4; base < NNZ_UI; base += nw * 4) {
        int e = base + sub;                 // NNZ_UI % 4 == 0 -> always valid
        int s = __ldg(src + e), d = __ldg(dst + e);
        float wt = __ldg(w + e);
        float4 ev = __ldg(Eu4 + s * 16 + hq + q);
        atomicAdd(B4 + d * 8 + q, scale4(wt, ev));
    }
}

// u2[s, hcols] += w * i1h[d]   (4 edges/warp)
__global__ void k_edge_u2h(const int* __restrict__ src, const int* __restrict__ dst,
                           const float* __restrict__ w, int hbase) {
    int tid = blockIdx.x * blockDim.x + threadIdx.x;
    int warp = tid >> 5, lane = tid & 31;
    int sub = lane >> 3, q = lane & 7;
    int nw = (gridDim.x * blockDim.x) >> 5;
    int hq = hbase >> 2;
    const float4* B4 = (const float4*)g_buf;
    float4* U4 = (float4*)g_u2;
    for (int base = warp * 4; base < NNZ_UI; base += nw * 4) {
        int e = base + sub;
        int s = __ldg(src + e), d = __ldg(dst + e);
        float wt = __ldg(w + e);
        float4 iv = __ldg(B4 + d * 8 + q);
        atomicAdd(U4 + s * 16 + hq + q, scale4(wt, iv));
    }
}

// itw partial for this half
__global__ void k_itw_h(const int* __restrict__ pos_items, const float* __restrict__ lw,
                        const float* __restrict__ Ei, int hbase) {
    int wi = threadIdx.x >> 5, lane = threadIdx.x & 31;
    int b = blockIdx.x * 8 + wi;
    if (b >= BSZ) return;
    int r = pos_items[b];
    float nw0, nw1, nw2;
    softmax3(lw, nw0, nw1, nw2);
    float c0 = nw0 + 0.1f * nw2;
    g_itw[b * 64 + hbase + lane] =
        c0 * __ldg(Ei + r * 64 + hbase + lane) + nw1 * g_buf[r * 32 + lane];
}

// ------------------------- u1 full + i2 + uw partial -----------------------
__global__ void k_u1_init(const float* __restrict__ Eu) {
    int i = blockIdx.x * blockDim.x + threadIdx.x;
    int stride = gridDim.x * blockDim.x;
    const float4* Eu4 = (const float4*)Eu;
    float4* b4 = (float4*)g_buf;
    for (int j = i; j < U_N * 16; j += stride) {
        float4 v = Eu4[j];
        v.x *= 0.1f; v.y *= 0.1f; v.z *= 0.1f; v.w *= 0.1f;
        b4[j] = v;
    }
}

// u1[s] += w * Ei[d]   (2 edges/warp, 16 lanes/edge, f4 ops)
__global__ void k_edge_u1(const int* __restrict__ src, const int* __restrict__ dst,
                          const float* __restrict__ w, const float* __restrict__ Ei) {
    int tid = blockIdx.x * blockDim.x + threadIdx.x;
    int warp = tid >> 5, lane = tid & 31;
    int sub = lane >> 4, q = lane & 15;
    int nw = (gridDim.x * blockDim.x) >> 5;
    const float4* Ei4 = (const float4*)Ei;
    float4* B4 = (float4*)g_buf;
    for (int base = warp * 2; base < NNZ_UI; base += nw * 2) {
        int e = base + sub;                 // NNZ_UI % 2 == 0
        int s = __ldg(src + e), d = __ldg(dst + e);
        float wt = __ldg(w + e);
        float4 ev = __ldg(Ei4 + d * 16 + q);
        atomicAdd(B4 + s * 16 + q, scale4(wt, ev));
    }
}

// i2b[slot_i[d]] += w * u1[s]  (selected items; 2 edges/warp)
__global__ void k_edge_i2(const int* __restrict__ src, const int* __restrict__ dst,
                          const float* __restrict__ w) {
    int tid = blockIdx.x * blockDim.x + threadIdx.x;
    int warp = tid >> 5, lane = tid & 31;
    int sub = lane >> 4, q = lane & 15;
    int nw = (gridDim.x * blockDim.x) >> 5;
    const float4* U14 = (const float4*)g_buf;
    float4* I4 = (float4*)g_i2b;
    for (int base = warp * 2; base < NNZ_UI; base += nw * 2) {
        int e = base + sub;
        int d = __ldg(dst + e);
        int v = g_slot_i[d];
        if (v < 0) continue;
        int s = __ldg(src + e);
        float wt = __ldg(w + e);
        float4 uv = __ldg(U14 + s * 16 + q);
        atomicAdd(I4 + v * 16 + q, scale4(wt, uv));
    }
}

// fin[b, 0:64] = nw0*Eu[r] + nw1*u1[r]   (u1 still in buf)
__global__ void k_fin_uw(const int* __restrict__ users, const float* __restrict__ lw,
                         const float* __restrict__ Eu) {
    int wi = threadIdx.x >> 5, lane = threadIdx.x & 31;
    int b = blockIdx.x * 8 + wi;
    if (b >= BSZ) return;
    int r = users[b];
    float nw0, nw1, nw2;
    softmax3(lw, nw0, nw1, nw2);
    g_fin[b * 128 + lane]      = nw0 * __ldg(Eu + r * 64 + lane)      + nw1 * g_buf[r * 64 + lane];
    g_fin[b * 128 + lane + 32] = nw0 * __ldg(Eu + r * 64 + lane + 32) + nw1 * g_buf[r * 64 + lane + 32];
}

// ------------------------- social layer 1 ----------------------------------
__global__ void k_zero_buf() {
    int i = blockIdx.x * blockDim.x + threadIdx.x;
    int stride = gridDim.x * blockDim.x;
    float4 z = make_float4(0.f, 0.f, 0.f, 0.f);
    float4* b4 = (float4*)g_buf;
    for (int j = i; j < U_N * 16; j += stride) b4[j] = z;
}

// Z[s] += w * u2[d]   (2 edges/warp)
__global__ void k_edge_Z(const int* __restrict__ src, const int* __restrict__ dst,
                         const float* __restrict__ w) {
    int tid = blockIdx.x * blockDim.x + threadIdx.x;
    int warp = tid >> 5, lane = tid & 31;
    int sub = lane >> 4, q = lane & 15;
    int nw = (gridDim.x * blockDim.x) >> 5;
    const float4* U24 = (const float4*)g_u2;
    float4* B4 = (float4*)g_buf;
    for (int base = warp * 2; base < NNZ_S; base += nw * 2) {
        int e = base + sub;                 // NNZ_S % 2 == 0
        int s = __ldg(src + e), d = __ldg(dst + e);
        float wt = __ldg(w + e);
        float4 uv = __ldg(U24 + d * 16 + q);
        atomicAdd(B4 + s * 16 + q, scale4(wt, uv));
    }
}

// c1 = gate(u2 + Z@W0, u2), written over Z in place (row-local)
__global__ void k_gate1(const float* __restrict__ W0, const float* __restrict__ hoW,
                        const float* __restrict__ hob, const float* __restrict__ hog,
                        const float* __restrict__ hobeta) {
    __shared__ float sW0[64 * 64];
    __shared__ float sHW[64 * 64];
    __shared__ float sRow[8][64];
    for (int i = threadIdx.x; i < 64 * 64; i += blockDim.x) { sW0[i] = W0[i]; sHW[i] = hoW[i]; }
    __syncthreads();
    int wi = threadIdx.x >> 5, lane = threadIdx.x & 31;
    int row = blockIdx.x * 8 + wi;
    if (row >= U_N) return;

    float2 zv = ((const float2*)g_buf)[row * 32 + lane];
    sRow[wi][2 * lane] = zv.x; sRow[wi][2 * lane + 1] = zv.y;
    __syncwarp();
    float zw0 = 0.f, zw1 = 0.f;
#pragma unroll
    for (int k = 0; k < 64; k++) {
        float zk = sRow[wi][k];
        zw0 = fmaf(zk, sW0[k * 64 + lane], zw0);
        zw1 = fmaf(zk, sW0[k * 64 + lane + 32], zw1);
    }
    float u20 = g_u2[row * 64 + lane], u21 = g_u2[row * 64 + lane + 32];
    float n0 = u20 + zw0, n1 = u21 + zw1;        // new1
    __syncwarp();
    sRow[wi][lane] = n0; sRow[wi][lane + 32] = n1;
    __syncwarp();
    float h0 = hob[lane], h1 = hob[lane + 32];
#pragma unroll
    for (int k = 0; k < 64; k++) {
        float nk = sRow[wi][k];
        h0 = fmaf(nk, sHW[k * 64 + lane], h0);
        h1 = fmaf(nk, sHW[k * 64 + lane + 32], h1);
    }
    float gt0, gt1;
    gate_from_h(h0, h1, hog, hobeta, lane, gt0, gt1);
    g_buf[row * 64 + lane]      = gt0 * n0 + (1.0f - gt0) * u20;
    g_buf[row * 64 + lane + 32] = gt1 * n1 + (1.0f - gt1) * u21;
}

// ------------------------- social layer 2 (selected) -----------------------
// zbf[slot_u[s]] += w * c1[d]   (2 edges/warp)
__global__ void k_edge_s2(const int* __restrict__ src, const int* __restrict__ dst,
                          const float* __restrict__ w) {
    int tid = blockIdx.x * blockDim.x + threadIdx.x;
    int warp = tid >> 5, lane = tid & 31;
    int sub = lane >> 4, q = lane & 15;
    int nw = (gridDim.x * blockDim.x) >> 5;
    const float4* C4 = (const float4*)g_buf;
    float4* Z4 = (float4*)g_zbf;
    for (int base = warp * 2; base < NNZ_S; base += nw * 2) {
        int e = base + sub;
        int s = __ldg(src + e);
        int v = g_slot_u[s];
        if (v < 0) continue;
        int d = __ldg(dst + e);
        float wt = __ldg(w + e);
        float4 cv = __ldg(C4 + d * 16 + q);
        atomicAdd(Z4 + v * 16 + q, scale4(wt, cv));
    }
}

// per selected user: gate layer 2, assemble sw and finish uw
__global__ void k_user_fin(const int* __restrict__ users, const float* __restrict__ lw,
                           const float* __restrict__ W1, const float* __restrict__ hoW,
                           const float* __restrict__ hob, const float* __restrict__ hog,
                           const float* __restrict__ hobeta) {
    __shared__ float sW1[64 * 64];
    __shared__ float sHW[64 * 64];
    __shared__ float sRow[8][64];
    for (int i = threadIdx.x; i < 64 * 64; i += blockDim.x) { sW1[i] = W1[i]; sHW[i] = hoW[i]; }
    __syncthreads();
    int wi = threadIdx.x >> 5, lane = threadIdx.x & 31;
    int b = blockIdx.x * 8 + wi;
    if (b >= BSZ) return;
    int r = users[b];
    int v = g_slot_u[r];
    float nw0, nw1, nw2;
    softmax3(lw, nw0, nw1, nw2);

    float2 zv = ((const float2*)g_zbf)[v * 32 + lane];
    sRow[wi][2 * lane] = zv.x; sRow[wi][2 * lane + 1] = zv.y;
    __syncwarp();
    float zw0 = 0.f, zw1 = 0.f;
#pragma unroll
    for (int k = 0; k < 64; k++) {
        float zk = sRow[wi][k];
        zw0 = fmaf(zk, sW1[k * 64 + lane], zw0);
        zw1 = fmaf(zk, sW1[k * 64 + lane + 32], zw1);
    }
    float c10 = g_buf[r * 64 + lane], c11 = g_buf[r * 64 + lane + 32];
    float n0 = c10 + zw0, n1 = c11 + zw1;        // new2
    __syncwarp();
    sRow[wi][lane] = n0; sRow[wi][lane + 32] = n1;
    __syncwarp();
    float h0 = hob[lane], h1 = hob[lane + 32];
#pragma unroll
    for (int k = 0; k < 64; k++) {
        float nk = sRow[wi][k];
        h0 = fmaf(nk, sHW[k * 64 + lane], h0);
        h1 = fmaf(nk, sHW[k * 64 + lane + 32], h1);
    }
    float gt0, gt1;
    gate_from_h(h0, h1, hog, hobeta, lane, gt0, gt1);
    float s20 = gt0 * n0 + (1.0f - gt0) * c10;
    float s21 = gt1 * n1 + (1.0f - gt1) * c11;

    float u20 = g_u2[r * 64 + lane], u21 = g_u2[r * 64 + lane + 32];
    g_fin[b * 128 + 64 + lane] = nw0 * u20 + nw1 * c10 + nw2 * s20;
    g_fin[b * 128 + 96 + lane] = nw0 * u21 + nw1 * c11 + nw2 * s21;
    g_fin[b * 128 + lane]      += nw2 * u20;     // finish uw
    g_fin[b * 128 + lane + 32] += nw2 * u21;
}

// ------------------------- metapath fusion ---------------------------------
__global__ void k_metapath(const float* __restrict__ mpW, const float* __restrict__ mpb,
                           const float* __restrict__ mpg, const float* __restrict__ mpbeta) {
    __shared__ float sW[128 * 64];
    __shared__ float sF[8][128];
    for (int i = threadIdx.x; i < 128 * 64; i += blockDim.x) sW[i] = mpW[i];
    __syncthreads();
    int wi = threadIdx.x >> 5, lane = threadIdx.x & 31;
    int b = blockIdx.x * 8 + wi;
    if (b >= BSZ) return;
    float4 f = ((const float4*)g_fin)[b * 32 + lane];
    sF[wi][4 * lane] = f.x; sF[wi][4 * lane + 1] = f.y;
    sF[wi][4 * lane + 2] = f.z; sF[wi][4 * lane + 3] = f.w;
    __syncwarp();
    float h0 = mpb[lane], h1 = mpb[lane + 32];
#pragma unroll
    for (int k = 0; k < 128; k++) {
        float fk = sF[wi][k];
        h0 = fmaf(fk, sW[k * 64 + lane], h0);
        h1 = fmaf(fk, sW[k * 64 + lane + 32], h1);
    }
    float s = warpSum(h0 + h1);
    float q = warpSum(h0 * h0 + h1 * h1);
    float mu = s * (1.0f / 64.0f);
    float var = q * (1.0f / 64.0f) - mu * mu;
    float inv = rsqrtf(var + 1e-5f);
    g_fus[b * 64 + lane]      = lrelu((h0 - mu) * inv * mpg[lane] + mpbeta[lane]);
    g_fus[b * 64 + lane + 32] = lrelu((h1 - mu) * inv * mpg[lane + 32] + mpbeta[lane + 32]);
}

// ------------------------- score -------------------------------------------
__global__ void k_score(const int* __restrict__ pos_items, const float* __restrict__ lw,
                        float* __restrict__ out) {
    int wi = threadIdx.x >> 5, lane = threadIdx.x & 31;
    int b = blockIdx.x * 8 + wi;
    if (b >= BSZ) return;
    int v = g_slot_i[pos_items[b]];
    float nw0, nw1, nw2;
    softmax3(lw, nw0, nw1, nw2);
    float2 fu = ((const float2*)g_fus)[b * 32 + lane];
    float2 it = ((const float2*)g_itw)[b * 32 + lane];
    float2 i2 = ((const float2*)g_i2b)[v * 32 + lane];
    float p = warpSum(fu.x * (it.x + nw2 * i2.x) + fu.y * (it.y + nw2 * i2.y));
    if (lane == 0) out[b] = p;
}

// ---------------------------------------------------------------------------
extern "C" void kernel_launch(void* const* d_in, const int* in_sizes, int n_in,
                              void* d_out, int out_size) {
    const int*   users   = (const int*)d_in[0];
    const int*   pos_it  = (const int*)d_in[1];
    const int*   ui_src  = (const int*)d_in[2];
    const int*   ui_dst  = (const int*)d_in[3];
    const float* ui_w    = (const float*)d_in[4];
    const int*   s_src   = (const int*)d_in[5];
    const int*   s_dst   = (const int*)d_in[6];
    const float* s_w     = (const float*)d_in[7];
    const float* Eu      = (const float*)d_in[8];
    const float* Ei      = (const float*)d_in[9];
    const float* lw      = (const float*)d_in[10];
    const float* Wsoc    = (const float*)d_in[11];
    const float* ho_W    = (const float*)d_in[12];
    const float* ho_b    = (const float*)d_in[13];
    const float* ho_g    = (const float*)d_in[14];
    const float* ho_beta = (const float*)d_in[15];
    const float* mp_W    = (const float*)d_in[16];
    const float* mp_b    = (const float*)d_in[17];
    const float* mp_g    = (const float*)d_in[18];
    const float* mp_beta = (const float*)d_in[19];
    float* out = (float*)d_out;

    k_init<<<1024, 256>>>(Eu);
    k_slots<<<16, 256>>>(users, pos_it);

    // LightGCN: i1 in column halves (arena), u2 accumulates full width
    for (int h = 0; h < 2; h++) {
        int hbase = h * 32;
        k_i1h_init<<<2048, 256>>>(Ei, hbase);
        k_edge_i1h<<<4096, 256>>>(ui_src, ui_dst, ui_w, Eu, hbase);
        k_edge_u2h<<<4096, 256>>>(ui_src, ui_dst, ui_w, hbase);
        k_itw_h<<<BSZ / 8, 256>>>(pos_it, lw, Ei, hbase);
    }

    // u1 full (arena), i2 at selected items, uw partial
    k_u1_init<<<1024, 256>>>(Eu);
    k_edge_u1<<<4096, 256>>>(ui_src, ui_dst, ui_w, Ei);
    k_edge_i2<<<4096, 256>>>(ui_src, ui_dst, ui_w);
    k_fin_uw<<<BSZ / 8, 256>>>(users, lw, Eu);

    // Social layer 1: Z = S@u2 (arena), fused GEMV+gate -> c1 (arena, in place)
    k_zero_buf<<<1024, 256>>>();
    k_edge_Z<<<2048, 256>>>(s_src, s_dst, s_w);
    k_gate1<<<(U_N + 7) / 8, 256>>>(Wsoc, ho_W, ho_b, ho_g, ho_beta);

    // Social layer 2 at selected users + assemble fin
    k_edge_s2<<<2048, 256>>>(s_src, s_dst, s_w);
    k_user_fin<<<BSZ / 8, 256>>>(users, lw, Wsoc + 64 * 64, ho_W, ho_b, ho_g, ho_beta);

    // metapath fusion + score
    k_metapath<<<BSZ / 8, 256>>>(mp_W, mp_b, mp_g, mp_beta);
    k_score<<<BSZ / 8, 256>>>(pos_it, lw, out);
}